// round 17
// baseline (speedup 1.0000x reference)
#include <cuda_runtime.h>
#include <stdint.h>

// ---------------------------------------------------------------------------
// BboxSegEnsembler: bandwidth-bound seg gather (masked 8-load, grid-stride)
// fused block-wise with a 6-stage topk/NMS detection chain.
// Output (float32): [ seg (2*192^3) | dets (100,8) | labels (100) ]
// ---------------------------------------------------------------------------

#define IMGD   192
#define IMGV   (192*192*192)
#define NPROP  200000
#define KPRE   1000
#define MAXPER 100
#define CAND_CAP 2048
#define NWORDS 16
#define QTOT   1769472          // 192*192*48 z-quads

typedef unsigned long long u64;

// ---------------- device scratch ------------------------------------------
__device__ unsigned int g_hist[65536];
__device__ unsigned int g_candCount;
__device__ unsigned int g_pivot;
__device__ u64          g_key[NPROP];
__device__ u64          g_cand[CAND_CAP];
__device__ float        g_bo[KPRE * 6];
__device__ float        g_boxOut[KPRE * 6];
__device__ float        g_vol[KPRE];
__device__ float        g_score[KPRE];
__device__ int          g_lab[KPRE];
__device__ u64          g_validw[NWORDS];
__device__ u64          g_mask[16384];       // rows 1000..1023 stay 0

__device__ __forceinline__ unsigned key32(float f) {
    unsigned u = __float_as_uint(f);
    return (u & 0x80000000u) ? ~u : (u | 0x80000000u);
}

// ---------------- seg gather: masked 8-load, grid-stride -------------------
// last-writer origin per axis: v<48 -> 0 ; v<96 -> 48 ; else 96
// coverage 2 iff 48<=v<144 (second covering origin = last-48 -> local +48)
__device__ __forceinline__ void seg_range(
    int qlo, int qhi, int segId, int nSeg,
    const float* __restrict__ tiles, const float* __restrict__ w,
    float* __restrict__ out)
{
    const float4* W = (const float4*)w;
    const float4* T = (const float4*)tiles;
    float4*       O = (float4*)out;
    const float4 z4 = make_float4(0.f, 0.f, 0.f, 0.f);
    int stride = nSeg * blockDim.x;
    for (int q = qlo + segId * blockDim.x + (int)threadIdx.x; q < qhi; q += stride) {
        int zq = q % 48;
        int r  = q / 48;
        int y  = r % IMGD;
        int x  = r / IMGD;
        int z  = zq * 4;

        int ox = (x < 48) ? 0 : ((x < 96) ? 48 : 96);
        int oy = (y < 48) ? 0 : ((y < 96) ? 48 : 96);
        int oz = (z < 48) ? 0 : ((z < 96) ? 48 : 96);
        bool hx = (x >= 48 && x < 144);
        bool hy = (y >= 48 && y < 144);
        bool hz = (z >= 48 && z < 144);

        // quad-index into (96,96,96): lx*2304 + ly*24 + lz/4
        int bq = (x - ox) * 2304 + (y - oy) * 24 + ((z - oz) >> 2);

        // 8 independent predicated loads (deltas +48 in each axis, in quads)
        float4 f0 = W[bq];
        float4 f1 = hx ? W[bq + 110592] : z4;            // +48x
        float4 f2 = hy ? W[bq + 1152]   : z4;            // +48y
        float4 f3 = hz ? W[bq + 12]     : z4;            // +48z
        float4 f4 = (hx && hy) ? W[bq + 111744] : z4;
        float4 f5 = (hx && hz) ? W[bq + 110604] : z4;
        float4 f6 = (hy && hz) ? W[bq + 1164]   : z4;
        float4 f7 = (hx && hy && hz) ? W[bq + 111756] : z4;

        float4 cnt;
        cnt.x = ((f0.x + f1.x) + (f2.x + f3.x)) + ((f4.x + f5.x) + (f6.x + f7.x));
        cnt.y = ((f0.y + f1.y) + (f2.y + f3.y)) + ((f4.y + f5.y) + (f6.y + f7.y));
        cnt.z = ((f0.z + f1.z) + (f2.z + f3.z)) + ((f4.z + f5.z) + (f6.z + f7.z));
        cnt.w = ((f0.w + f1.w) + (f2.w + f3.w)) + ((f4.w + f5.w) + (f6.w + f7.w));

        float4 rr;   // wl == f0 (primary combo is the last-writer local coord)
        rr.x = __fdividef(f0.x, cnt.x);
        rr.y = __fdividef(f0.y, cnt.y);
        rr.z = __fdividef(f0.z, cnt.z);
        rr.w = __fdividef(f0.w, cnt.w);

        int ti = (ox / 48) * 9 + (oy / 48) * 3 + (oz / 48);
        int tq = ti * 442368 + bq;                 // 2*96^3/4 quads per tile
        float4 t0 = T[tq];
        float4 t1 = T[tq + 221184];

        int oq = x * 9216 + y * 48 + (z >> 2);     // output z-quads
        O[oq]        = make_float4(t0.x*rr.x, t0.y*rr.y, t0.z*rr.z, t0.w*rr.w);
        O[oq + QTOT] = make_float4(t1.x*rr.x, t1.y*rr.y, t1.z*rr.z, t1.w*rr.w);
    }
}

// ---------------- K1 (512 thr): key pack + histogram (+seg) ----------------
#define K1_DET 391
__global__ __launch_bounds__(512) void k1_hist(
    const float* __restrict__ bb, const float* __restrict__ tiles,
    const float* __restrict__ w, float* __restrict__ out)
{
    if (blockIdx.x < K1_DET) {
        int gid = blockIdx.x * 512 + threadIdx.x;
        if (gid < NPROP) {
            unsigned k = key32(bb[gid * 7 + 6]);
            g_key[gid] = ((u64)k << 32) | (unsigned)(~gid);   // lower idx wins ties
            atomicAdd(&g_hist[k >> 16], 1u);
        }
    } else {
        seg_range(0, 230000, (int)blockIdx.x - K1_DET, (int)gridDim.x - K1_DET,
                  tiles, w, out);
    }
}

// ---------------- K2 (1024 thr): pivot (proven suffix scan) (+seg) ---------
__global__ __launch_bounds__(1024) void k2_pivot(
    const float* __restrict__ tiles, const float* __restrict__ w,
    float* __restrict__ out)
{
    if (blockIdx.x == 0) {
        __shared__ unsigned part[1024];
        int t = threadIdx.x;
        if (t == 0) g_candCount = 0;
        if (t < NWORDS) g_validw[t] = 0ULL;
        unsigned s = 0;
        #pragma unroll 8
        for (int e = 0; e < 64; e++) s += g_hist[t * 64 + e];
        part[t] = s;
        __syncthreads();
        for (int off = 1; off < 1024; off <<= 1) {     // suffix sum
            unsigned v = (t + off < 1024) ? part[t + off] : 0u;
            __syncthreads();
            part[t] += v;
            __syncthreads();
        }
        unsigned mine = part[t];
        unsigned nxt  = (t == 1023) ? 0u : part[t + 1];
        if (mine >= KPRE && nxt < KPRE) {
            unsigned acc = nxt;
            int p = t * 64;
            for (int b = 63; b >= 0; b--) {
                acc += g_hist[t * 64 + b];
                if (acc >= KPRE) { p = t * 64 + b; break; }
            }
            g_pivot = (unsigned)p;
        }
    } else {
        seg_range(230000, 384000, (int)blockIdx.x - 1, (int)gridDim.x - 1,
                  tiles, w, out);
    }
}

// ---------------- K3 (512 thr): collect + re-zero hist (+seg) --------------
#define K3_DET 391
__global__ __launch_bounds__(512) void k3_collect(
    const float* __restrict__ tiles, const float* __restrict__ w,
    float* __restrict__ out)
{
    if (blockIdx.x < K3_DET) {
        int gid = blockIdx.x * 512 + threadIdx.x;
        if (gid < 65536) g_hist[gid] = 0;          // idempotence across replays
        if (gid < NPROP) {
            u64 kk = g_key[gid];
            if ((unsigned)(kk >> 48) >= g_pivot) {
                unsigned pos = atomicAdd(&g_candCount, 1u);
                if (pos < CAND_CAP) g_cand[pos] = kk;
            }
        }
    } else {
        seg_range(384000, 538000, (int)blockIdx.x - K3_DET, (int)gridDim.x - K3_DET,
                  tiles, w, out);
    }
}

// ---------------- K4 (1024 thr): proven full bitonic 2048 + prep (+seg) ----
__global__ __launch_bounds__(1024) void k4_sort_prep(
    const float* __restrict__ bb, const int* __restrict__ labels,
    const float* __restrict__ tiles, const float* __restrict__ w,
    float* __restrict__ out)
{
    if (blockIdx.x == 0) {
        __shared__ u64 s[CAND_CAP];
        int t = threadIdx.x;
        unsigned cc = g_candCount; if (cc > CAND_CAP) cc = CAND_CAP;
        s[t]        = (t        < (int)cc) ? g_cand[t]        : 0ULL;
        s[t + 1024] = (t + 1024 < (int)cc) ? g_cand[t + 1024] : 0ULL;
        __syncthreads();
        // classic bitonic network, descending (proven pattern from R12 PASS)
        for (int k = 2; k <= CAND_CAP; k <<= 1) {
            for (int j = k >> 1; j > 0; j >>= 1) {
                #pragma unroll
                for (int h = 0; h < 2; h++) {
                    int e = t + h * 1024;
                    int exj = e ^ j;
                    if (exj > e) {
                        u64 a = s[e], b = s[exj];
                        bool desc = ((e & k) == 0);
                        if (desc ? (a < b) : (a > b)) { s[e] = b; s[exj] = a; }
                    }
                }
                __syncthreads();
            }
        }

        // ---- fused prep: clip, validity, class offset, volume ----
        int r = t;
        if (r < KPRE) {
            int i = (int)(~(unsigned)(s[r] & 0xFFFFFFFFu));
            float p[6];
            #pragma unroll
            for (int d = 0; d < 6; d++)
                p[d] = fminf(fmaxf(bb[i * 7 + d], 0.0f), 192.0f);
            float sc = bb[i * 7 + 6];
            bool valid = (sc > 0.01f)
                       && (p[3] - p[0] >= 0.01f)
                       && (p[4] - p[1] >= 0.01f)
                       && (p[5] - p[2] >= 0.01f);
            int lab = labels[i];
            float off = (float)lab * 384.0f;       // CLASS_OFFSET = 2*192
            float bo[6];
            #pragma unroll
            for (int d = 0; d < 6; d++) {
                bo[d] = p[d] + off;
                g_bo[r * 6 + d] = bo[d];
                g_boxOut[r * 6 + d] = p[d];
            }
            g_vol[r]   = ((bo[3] - bo[0]) * (bo[4] - bo[1])) * (bo[5] - bo[2]);
            g_score[r] = sc;
            g_lab[r]   = lab;
            if (valid) atomicOr(&g_validw[r >> 6], 1ULL << (r & 63));
        }
    } else {
        seg_range(538000, 1307472, (int)blockIdx.x - 1, (int)gridDim.x - 1,
                  tiles, w, out);
    }
}

// ---------------- K5 (1024 thr): IoU suppression bitmask (+seg) ------------
__global__ __launch_bounds__(1024) void k5_mask(
    const float* __restrict__ tiles, const float* __restrict__ w,
    float* __restrict__ out)
{
    if (blockIdx.x < 16) {
        __shared__ float sbox[KPRE][7];            // 28KB
        int t = threadIdx.x;
        for (int e = t; e < KPRE; e += 1024) {
            #pragma unroll
            for (int d = 0; d < 6; d++) sbox[e][d] = g_bo[e * 6 + d];
            sbox[e][6] = g_vol[e];
        }
        __syncthreads();
        int li = t & 63;                           // row within 64-row group
        int cg = t >> 6;                           // column word (warp-uniform)
        int i  = blockIdx.x * 64 + li;
        if (i < KPRE) {
            float m0 = sbox[i][0], m1 = sbox[i][1], m2 = sbox[i][2];
            float M0 = sbox[i][3], M1 = sbox[i][4], M2 = sbox[i][5];
            float vi = sbox[i][6];
            u64 bits = 0ULL;
            int j0 = cg * 64;
            int jmax = KPRE - j0; if (jmax > 64) jmax = 64;
            for (int jj = 0; jj < jmax; jj++) {
                const float* B = sbox[j0 + jj];
                float i0 = fmaxf(fminf(M0, B[3]) - fmaxf(m0, B[0]), 0.0f);
                float i1 = fmaxf(fminf(M1, B[4]) - fmaxf(m1, B[1]), 0.0f);
                float i2 = fmaxf(fminf(M2, B[5]) - fmaxf(m2, B[2]), 0.0f);
                float inter = (i0 * i1) * i2;
                float uni = vi + B[6] - inter;
                float iou = inter / fmaxf(uni, 1e-6f);
                if (iou > 0.1f) bits |= (1ULL << jj);
            }
            g_mask[i * NWORDS + cg] = bits;
        }
    } else {
        seg_range(1307472, 1538472, (int)blockIdx.x - 16, (int)gridDim.x - 16,
                  tiles, w, out);
    }
}

// ---------------- K6 (1024 thr): NMS early-exit + output (+seg) ------------
__global__ __launch_bounds__(1024) void k6_nms(
    const float* __restrict__ tiles, const float* __restrict__ w,
    float* __restrict__ out, float* __restrict__ outDet,
    float* __restrict__ outLab)
{
    if (blockIdx.x == 0) {
        __shared__ u64 sm[1024];                   // 64 rows x 16 words
        __shared__ int s_fidx[MAXPER];
        __shared__ int s_nk;
        __shared__ int s_done;
        int t = threadIdx.x;
        if (t == 0) { s_nk = 0; s_done = 0; }
        u64 remv = 0ULL;
        int nk = 0;
        __syncthreads();

        for (int b = 0; b < NWORDS; b++) {
            sm[t] = g_mask[b * 1024 + t];
            __syncthreads();
            if (t < 32) {
                int lane = t;
                u64 alive = g_validw[b] & ~__shfl_sync(0xFFFFFFFFu, remv, b);
                while (alive && nk < MAXPER) {
                    int il = __ffsll((long long)alive) - 1;
                    if (lane == 0) s_fidx[nk] = b * 64 + il;
                    nk++;
                    u64 rowL = (lane < NWORDS) ? sm[il * 16 + lane] : 0ULL;
                    remv |= rowL;
                    u64 rowb = sm[il * 16 + b];
                    alive &= ~rowb;
                    alive &= ~(1ULL << il);
                }
                if (lane == 0 && (nk >= MAXPER || b == NWORDS - 1)) {
                    s_nk = nk;
                    s_done = (nk >= MAXPER) ? 1 : 0;
                }
            }
            __syncthreads();
            if (s_done) break;
        }

        int nkf = s_nk;
        for (int e = t; e < MAXPER * 8; e += 1024) {
            int sidx = e >> 3, c = e & 7;
            float v = 0.0f;
            if (sidx < nkf) {
                int r = s_fidx[sidx];
                v = (c < 6) ? g_boxOut[r * 6 + c] : g_score[r];
            }
            outDet[e] = v;
        }
        for (int sidx = t; sidx < MAXPER; sidx += 1024)
            outLab[sidx] = (sidx < nkf) ? (float)g_lab[s_fidx[sidx]] : -1.0f;
    } else {
        seg_range(1538472, 1769472, (int)blockIdx.x - 1, (int)gridDim.x - 1,
                  tiles, w, out);
    }
}

// ---------------------------------------------------------------------------
extern "C" void kernel_launch(void* const* d_in, const int* in_sizes, int n_in,
                              void* d_out, int out_size) {
    const float* tiles  = (const float*)d_in[0];
    const float* w      = (const float*)d_in[1];
    const float* bb     = (const float*)d_in[2];
    const int*   labels = (const int*)d_in[3];
    // d_in[4] = tile_origins: fixed meshgrid, folded analytically
    float* out    = (float*)d_out;
    float* outDet = out + 2 * IMGV;
    float* outLab = outDet + MAXPER * 8;

    // seg ranges (qids) ~ proportional to det stage cost, sum = 1769472
    k1_hist     <<<K1_DET + 200, 512 >>>(bb, tiles, w, out);
    k2_pivot    <<<1      + 146, 1024>>>(tiles, w, out);
    k3_collect  <<<K3_DET + 150, 512 >>>(tiles, w, out);
    k4_sort_prep<<<1      + 145, 1024>>>(bb, labels, tiles, w, out);
    k5_mask     <<<16     + 140, 1024>>>(tiles, w, out);
    k6_nms      <<<1      + 145, 1024>>>(tiles, w, out, outDet, outLab);
}